// round 1
// baseline (speedup 1.0000x reference)
#include <cuda_runtime.h>
#include <cstdint>

typedef unsigned long long ull;

// Packed 2xFP32 FMA — only reachable via PTX fma.rn.f32x2 (ptxas never auto-fuses).
__device__ __forceinline__ ull ffma2(ull a, ull b, ull c) {
    ull d;
    asm("fma.rn.f32x2 %0, %1, %2, %3;" : "=l"(d) : "l"(a), "l"(b), "l"(c));
    return d;
}
__device__ __forceinline__ ull pk2(float a, float b) {
    ull r;
    unsigned ua = __float_as_uint(a), ub = __float_as_uint(b);
    asm("mov.b64 %0, {%1, %2};" : "=l"(r) : "r"(ua), "r"(ub));
    return r;
}
__device__ __forceinline__ float lo2(ull v) { return __uint_as_float((unsigned)(v & 0xffffffffull)); }
__device__ __forceinline__ float hi2(ull v) { return __uint_as_float((unsigned)(v >> 32)); }

#define BATCH 16
#define CIN   64
#define HD    128
#define WD    128
#define OC    128
#define CI    4          // input channels staged per K-iter
#define XROW  132        // padded smem row stride (16B-aligned float4 reads)
#define WROW  132

__global__ __launch_bounds__(256, 2)
void patchconv_kernel(const float* __restrict__ x, const float* __restrict__ wt,
                      const float* __restrict__ bias, float* __restrict__ out) {
    __shared__ __align__(16) float xs[3 * CI * XROW];   // 3 rows x CI ch x 130(+pad)
    __shared__ __align__(16) float ws[36 * WROW];       // (ci*9+r) x 128 o
    __shared__ __align__(16) float ssum[WD];            // patch_sum for this (b,h) row

    const int h   = blockIdx.x;
    const int b   = blockIdx.y;
    const int tid = threadIdx.x;
    const int og  = tid >> 4;      // 0..15 -> o-group
    const int wg  = tid & 15;      // 0..15 -> w-group
    const int o0  = og << 3;
    const int w0  = wg << 3;

    ull acc[4][8];                 // 4 o-pairs (8 o) x 8 w, packed fp32x2 over o
    #pragma unroll
    for (int i = 0; i < 4; i++)
        #pragma unroll
        for (int j = 0; j < 8; j++) acc[i][j] = 0ull;

    float s[8];                    // patch_sum partials (og==0 threads only)
    #pragma unroll
    for (int j = 0; j < 8; j++) s[j] = 0.f;

    const float* xb = x + (size_t)b * CIN * HD * WD;

    #pragma unroll 1
    for (int ci0 = 0; ci0 < CIN; ci0 += CI) {
        __syncthreads();
        // ---- stage x: rows h-1..h+1, CI channels, width padded to 130 ----
        for (int idx = tid; idx < 3 * CI * 130; idx += 256) {
            int kh  = idx / (CI * 130);
            int rem = idx - kh * (CI * 130);
            int ci  = rem / 130;
            int t   = rem - ci * 130;
            int hr  = h - 1 + kh;
            int wg_ = t - 1;
            float v = 0.f;
            if ((unsigned)hr < (unsigned)HD && (unsigned)wg_ < (unsigned)WD)
                v = xb[((size_t)(ci0 + ci) * HD + hr) * WD + wg_];
            xs[(kh * CI + ci) * XROW + t] = v;
        }
        // ---- stage weights: f = ci*9 + r (36 taps), o-contiguous rows ----
        for (int idx = tid; idx < 36 * OC; idx += 256) {
            int o = idx / 36;
            int f = idx - o * 36;
            ws[f * WROW + o] = wt[o * (CIN * 9) + ci0 * 9 + f];
        }
        __syncthreads();

        #pragma unroll
        for (int ci = 0; ci < CI; ci++) {
            #pragma unroll
            for (int kh = 0; kh < 3; kh++) {
                const float* xr = &xs[(kh * CI + ci) * XROW + w0];
                float4 a0 = *(const float4*)(xr);
                float4 a1 = *(const float4*)(xr + 4);
                float2 a2 = *(const float2*)(xr + 8);
                float xv[10] = {a0.x, a0.y, a0.z, a0.w,
                                a1.x, a1.y, a1.z, a1.w,
                                a2.x, a2.y};
                ull xp[10];
                #pragma unroll
                for (int t = 0; t < 10; t++) xp[t] = pk2(xv[t], xv[t]);

                if (og == 0) {   // patch_sum rides along on the same staged data
                    #pragma unroll
                    for (int j = 0; j < 8; j++) s[j] += xv[j] + xv[j + 1] + xv[j + 2];
                }

                #pragma unroll
                for (int kw = 0; kw < 3; kw++) {
                    const ulonglong2* wr =
                        (const ulonglong2*)&ws[(ci * 9 + kh * 3 + kw) * WROW + o0];
                    ulonglong2 p0 = wr[0];
                    ulonglong2 p1 = wr[1];
                    ull wp[4] = {p0.x, p0.y, p1.x, p1.y};
                    #pragma unroll
                    for (int i = 0; i < 4; i++)
                        #pragma unroll
                        for (int j = 0; j < 8; j++)
                            acc[i][j] = ffma2(wp[i], xp[j + kw], acc[i][j]);
                }
            }
        }
    }

    // ---- broadcast patch_sum across o-groups ----
    if (og == 0) {
        #pragma unroll
        for (int j = 0; j < 8; j++) ssum[w0 + j] = s[j];
    }
    __syncthreads();

    float cj[8];
    #pragma unroll
    for (int j = 0; j < 8; j++)
        cj[j] = 0.1f * (float)(h + w0 + j) * ssum[w0 + j];

    // ---- epilogue: unpack, add rank-1 term + bias, coalesced float4 stores ----
    #pragma unroll
    for (int i = 0; i < 4; i++) {
        #pragma unroll
        for (int half = 0; half < 2; half++) {
            int o = o0 + 2 * i + half;
            float bz = bias[o];
            float r[8];
            #pragma unroll
            for (int j = 0; j < 8; j++) {
                float p = half ? hi2(acc[i][j]) : lo2(acc[i][j]);
                r[j] = p + cj[j] + bz;
            }
            float* ob = out + (((size_t)b * OC + o) * HD + h) * WD + w0;
            *(float4*)(ob)     = make_float4(r[0], r[1], r[2], r[3]);
            *(float4*)(ob + 4) = make_float4(r[4], r[5], r[6], r[7]);
        }
    }
}

extern "C" void kernel_launch(void* const* d_in, const int* in_sizes, int n_in,
                              void* d_out, int out_size) {
    const float* x    = (const float*)d_in[0];
    const float* wt   = (const float*)d_in[1];
    const float* bias = (const float*)d_in[2];
    float* out        = (float*)d_out;
    dim3 grid(HD, BATCH);   // one CTA per (h, b): 128 x 16 = 2048 CTAs
    patchconv_kernel<<<grid, 256>>>(x, wt, bias, out);
}